// round 17
// baseline (speedup 1.0000x reference)
#include <cuda_runtime.h>
#include <cuda_fp16.h>
#include <math.h>
#include <stdint.h>

#define LDIM 384
#define NSEQ 512
#define DIN 128
#define HEADS 4
#define DFF 256
#define TOK (NSEQ*LDIM)      // 196608

// ---------------- scratch -----------------------------------------------------
__device__ __align__(256) float  g_attn [HEADS*LDIM*LDIM];   // symmetric logits
__device__ __align__(256) __half g_attnh[HEADS*LDIM*LDIM];   // softmax [h][l][k]
__device__ __align__(256) __half g_vh   [HEADS*NSEQ*16*LDIM];// v [h][(n,c)][k]
__device__ __align__(256) __half g_oh   [HEADS*TOK*16];      // o [h][token][16c]
__device__ __align__(256) __half g_Woh  [64*64];             // Wo, rows permuted, half
__device__ __align__(256) __half g_W1h  [64*DFF];            // W1 half
__device__ __align__(256) __half g_W2h  [DFF*64];            // W2 half

__device__ __forceinline__ float warpSum(float v) {
#pragma unroll
    for (int o = 16; o > 0; o >>= 1) v += __shfl_xor_sync(0xffffffffu, v, o);
    return v;
}
__device__ __forceinline__ uint32_t packh2(float x, float y) {
    __half2 h = __floats2half2_rn(x, y);
    return *(uint32_t*)&h;
}
__device__ __forceinline__ void mma_f16(float* c, const uint32_t* a, const uint32_t* b) {
    asm volatile(
        "mma.sync.aligned.m16n8k16.row.col.f32.f16.f16.f32 "
        "{%0,%1,%2,%3},{%4,%5,%6,%7},{%8,%9},{%0,%1,%2,%3};"
        : "+f"(c[0]), "+f"(c[1]), "+f"(c[2]), "+f"(c[3])
        : "r"(a[0]), "r"(a[1]), "r"(a[2]), "r"(a[3]), "r"(b[0]), "r"(b[1]));
}
__device__ __forceinline__ uint32_t s2u(const void* p) {
    uint32_t a;
    asm("{ .reg .u64 t; cvta.to.shared.u64 t, %1; cvt.u32.u64 %0, t; }"
        : "=r"(a) : "l"(p));
    return a;
}
__device__ __forceinline__ void ldmx2t(uint32_t& b0, uint32_t& b1, uint32_t addr) {
    asm volatile("ldmatrix.sync.aligned.m8n8.x2.trans.shared.b16 {%0,%1}, [%2];"
                 : "=r"(b0), "=r"(b1) : "r"(addr));
}
// x4 transposed: two adjacent 8-col B fragments (cols c..c+7 -> r0,r1; c+8..c+15 -> r2,r3)
__device__ __forceinline__ void ldmx4t(uint32_t* r, uint32_t addr) {
    asm volatile("ldmatrix.sync.aligned.m8n8.x4.trans.shared.b16 {%0,%1,%2,%3}, [%4];"
                 : "=r"(r[0]), "=r"(r[1]), "=r"(r[2]), "=r"(r[3]) : "r"(addr));
}
__device__ __forceinline__ void ldmx4(uint32_t* r, uint32_t addr) {
    asm volatile("ldmatrix.sync.aligned.m8n8.x4.shared.b16 {%0,%1,%2,%3}, [%4];"
                 : "=r"(r[0]), "=r"(r[1]), "=r"(r[2]), "=r"(r[3]) : "r"(addr));
}
__device__ __forceinline__ void cp16(uint32_t dst, const void* src) {
    asm volatile("cp.async.ca.shared.global [%0], [%1], 16;" :: "r"(dst), "l"(src));
}

// ---------------- logits body ------------------------------------------------
__device__ __forceinline__ void logits_pair(
    int k, int l,
    const float* __restrict__ src, const float* __restrict__ Wp,
    const float* __restrict__ bp, const float* __restrict__ gn,
    const float* __restrict__ btn, int lane)
{
    float4 a = *(const float4*)(src + ((size_t)k * LDIM + l) * DIN + lane * 4);
    float4 bb4 = *(const float4*)(src + ((size_t)l * LDIM + k) * DIN + lane * 4);
    float x0 = 0.5f * (a.x + bb4.x), x1 = 0.5f * (a.y + bb4.y);
    float x2 = 0.5f * (a.z + bb4.z), x3 = 0.5f * (a.w + bb4.w);

    float m = warpSum(x0 + x1 + x2 + x3) * (1.0f / 128.0f);
    float d0 = x0 - m, d1 = x1 - m, d2 = x2 - m, d3 = x3 - m;
    float var = warpSum(d0*d0 + d1*d1 + d2*d2 + d3*d3) * (1.0f / 128.0f);
    float rinv = rsqrtf(var + 1e-5f);

    int i0 = lane * 4;
    float4 g  = *(const float4*)(gn  + i0);
    float4 bt = *(const float4*)(btn + i0);
    float y0 = g.x * d0 * rinv + bt.x;
    float y1 = g.y * d1 * rinv + bt.y;
    float y2 = g.z * d2 * rinv + bt.z;
    float y3 = g.w * d3 * rinv + bt.w;

    const float4* Wp4 = (const float4*)Wp;
    float4 w0 = Wp4[i0 + 0], w1 = Wp4[i0 + 1], w2 = Wp4[i0 + 2], w3 = Wp4[i0 + 3];

    float h0 = y0*w0.x + y1*w1.x + y2*w2.x + y3*w3.x;
    float h1 = y0*w0.y + y1*w1.y + y2*w2.y + y3*w3.y;
    float h2 = y0*w0.z + y1*w1.z + y2*w2.z + y3*w3.z;
    float h3 = y0*w0.w + y1*w1.w + y2*w2.w + y3*w3.w;
    h0 = warpSum(h0); h1 = warpSum(h1); h2 = warpSum(h2); h3 = warpSum(h3);

    if (lane == 0) {
        size_t p1 = (size_t)k * LDIM + l;
        size_t p2 = (size_t)l * LDIM + k;
        float v0 = h0 + bp[0], v1 = h1 + bp[1], v2 = h2 + bp[2], v3 = h3 + bp[3];
        g_attn[0 * LDIM * LDIM + p1] = v0; g_attn[0 * LDIM * LDIM + p2] = v0;
        g_attn[1 * LDIM * LDIM + p1] = v1; g_attn[1 * LDIM * LDIM + p2] = v1;
        g_attn[2 * LDIM * LDIM + p1] = v2; g_attn[2 * LDIM * LDIM + p2] = v2;
        g_attn[3 * LDIM * LDIM + p1] = v3; g_attn[3 * LDIM * LDIM + p2] = v3;
    }
}

// ---------------- fused head kernel: logits(mirror) | vproj | diag | wprep --
#define NB_VP    (TOK/64)                // 3072
#define NB_MIX   (NB_VP*4)               // 12288 : 3 logits + 1 vproj
#define NB_DIAG  24
#define NB_HEAD  (NB_MIX + NB_DIAG + 64)

__global__ __launch_bounds__(256) void k_head(
    const float* __restrict__ src, const float* __restrict__ Wp,
    const float* __restrict__ bp, const float* __restrict__ gn,
    const float* __restrict__ btn,
    const float* __restrict__ tgt, const float* __restrict__ Wm,
    const float* __restrict__ bm, const float* __restrict__ g1,
    const float* __restrict__ bt1,
    const float* __restrict__ Wo, const float* __restrict__ W1,
    const float* __restrict__ W2)
{
    __shared__ __half Ah  [64 * 72];
    __shared__ __half Ws  [64 * 72];
    __shared__ __half Vout[64 * 72];

    int b = blockIdx.x;
    int tid = threadIdx.x, lane = tid & 31, wid = tid >> 5;

    if (b >= NB_MIX + NB_DIAG) {
        int i = (b - NB_MIX - NB_DIAG) * 256 + tid;
        if (i < 64 * 64) {
            int k = i >> 6, n = i & 63;
            int kp = (k & 3) * 16 + (k >> 2);
            g_Woh[kp * 64 + n] = __float2half_rn(Wo[i]);
        }
        if (i < 64 * DFF)  g_W1h[i] = __float2half_rn(W1[i]);
        if (i < DFF * 64)  g_W2h[i] = __float2half_rn(W2[i]);
        return;
    }
    if (b >= NB_MIX) {
        int kk = 192 + (b - NB_MIX) * 8 + wid;
        logits_pair(kk, kk, src, Wp, bp, gn, btn, lane);
        return;
    }

    int grp = b >> 2, rem = b & 3;

    if (rem < 3) {
        int w = (grp * 3 + rem) * 8 + wid;
        int k = w / LDIM, l = w - k * LDIM;
        if (k > l) { k = LDIM - 1 - k; l = LDIM - 1 - l; }
        logits_pair(k, l, src, Wp, bp, gn, btn, lane);
        return;
    }

    // ---- vproj body ----
    int r0 = grp * 64;
    int grpq = lane >> 2, tig = lane & 3, lk = lane & 15;
    int l8 = lane & 7, kq = ((lane >> 3) & 1) * 8, ch8 = (lane >> 4) * 8;
    __half2* Ah2 = (__half2*)Ah;
    __half2* Ws2 = (__half2*)Ws;
    uint32_t sAh = s2u(Ah), sWs = s2u(Ws);

#pragma unroll
    for (int rr = 0; rr < 8; rr++) {
        int row = wid * 8 + rr;
        float2 v = *(const float2*)(tgt + (size_t)(r0 + row) * 64 + lane * 2);
        float m = warpSum(v.x + v.y) * (1.0f / 64.0f);
        float d0 = v.x - m, d1 = v.y - m;
        float var = warpSum(d0*d0 + d1*d1) * (1.0f / 64.0f);
        float rinv = rsqrtf(var + 1e-5f);
        float2 gg = *(const float2*)(g1 + lane * 2);
        float2 bb2 = *(const float2*)(bt1 + lane * 2);
        Ah2[row * 36 + lane] = __floats2half2_rn(gg.x * d0 * rinv + bb2.x,
                                                 gg.y * d1 * rinv + bb2.y);
    }
#pragma unroll
    for (int i = 0; i < 4; i++) {
        int idx = tid + i * 256;
        int k = idx >> 4, n4 = (idx & 15) * 4;
        float4 w = *(const float4*)(Wm + k * 64 + n4);
        Ws2[k * 36 + n4 / 2    ] = __floats2half2_rn(w.x, w.y);
        Ws2[k * 36 + n4 / 2 + 1] = __floats2half2_rn(w.z, w.w);
    }
    __syncthreads();

    int wm = wid >> 1, wn = wid & 1;
    int m0 = wm * 16, nb = wn * 32;
    int aRow = m0 + lk, aCol = (lane >> 4) * 8;
    float c[4][4] = {};
#pragma unroll
    for (int kw = 0; kw < 4; kw++) {
        uint32_t a[4];
        ldmx4(a, sAh + (aRow * 72 + kw * 16 + aCol) * 2);
#pragma unroll
        for (int j = 0; j < 2; j++) {
            uint32_t b4[4];
            ldmx4t(b4, sWs + ((kw * 16 + l8 + kq) * 72 + nb + j * 16 + ch8) * 2);
            mma_f16(c[2 * j    ], a, &b4[0]);
            mma_f16(c[2 * j + 1], a, &b4[2]);
        }
    }
#pragma unroll
    for (int nt = 0; nt < 4; nt++) {
        int col = nb + nt * 8 + 2 * tig;
#pragma unroll
        for (int q = 0; q < 4; q++) {
            int rl = m0 + grpq + (q >= 2 ? 8 : 0);
            int cc = col + (q & 1);
            Vout[cc * 72 + rl] = __float2half_rn(c[nt][q] + bm[cc]);
        }
    }
    __syncthreads();
    int n = r0 / LDIM, k0g = r0 % LDIM;
#pragma unroll
    for (int i = 0; i < 2; i++) {
        int idx = tid + i * 256;
        int cc = idx >> 3, g8 = (idx & 7) * 8;
        uint4 v = *(uint4*)&Vout[cc * 72 + g8];
        __half* dst = &g_vh[(((size_t)(cc & 3) * NSEQ + n) * 16 + (cc >> 2)) * LDIM + k0g + g8];
        *(uint4*)dst = v;
    }
}

// ---------------- kernel 2: softmax, warp per row ---------------------------
__global__ __launch_bounds__(256) void k_softmax()
{
    int row = blockIdx.x * 8 + (threadIdx.x >> 5);
    int lane = threadIdx.x & 31;
    const float* p = g_attn + (size_t)row * LDIM;
    __half* q = g_attnh + (size_t)row * LDIM;

    float4 v0 = *(const float4*)(p + lane * 4);
    float4 v1 = *(const float4*)(p + 128 + lane * 4);
    float4 v2 = *(const float4*)(p + 256 + lane * 4);

    float mx = fmaxf(fmaxf(fmaxf(v0.x, v0.y), fmaxf(v0.z, v0.w)),
               fmaxf(fmaxf(fmaxf(v1.x, v1.y), fmaxf(v1.z, v1.w)),
                     fmaxf(fmaxf(v2.x, v2.y), fmaxf(v2.z, v2.w))));
#pragma unroll
    for (int o = 16; o > 0; o >>= 1) mx = fmaxf(mx, __shfl_xor_sync(0xffffffffu, mx, o));

    float e[12];
    e[0] = __expf(v0.x - mx); e[1] = __expf(v0.y - mx); e[2] = __expf(v0.z - mx); e[3] = __expf(v0.w - mx);
    e[4] = __expf(v1.x - mx); e[5] = __expf(v1.y - mx); e[6] = __expf(v1.z - mx); e[7] = __expf(v1.w - mx);
    e[8] = __expf(v2.x - mx); e[9] = __expf(v2.y - mx); e[10] = __expf(v2.z - mx); e[11] = __expf(v2.w - mx);

    float s = 0.f;
#pragma unroll
    for (int i = 0; i < 12; i++) s += e[i];
    s = warpSum(s);
    float rs = 1.0f / s;

    uint2 o0, o1, o2;
    o0.x = packh2(e[0] * rs, e[1] * rs);  o0.y = packh2(e[2] * rs, e[3] * rs);
    o1.x = packh2(e[4] * rs, e[5] * rs);  o1.y = packh2(e[6] * rs, e[7] * rs);
    o2.x = packh2(e[8] * rs, e[9] * rs);  o2.y = packh2(e[10] * rs, e[11] * rs);
    *(uint2*)(q + lane * 4)       = o0;
    *(uint2*)(q + 128 + lane * 4) = o1;
    *(uint2*)(q + 256 + lane * 4) = o2;
}

// ---------------- kernel 4: per-head attn GEMM fp16, coalesced epilogue -----
#define KA_ST 40
#define KA_STAGE (128*KA_ST)
__global__ __launch_bounds__(256, 2) void k_attn()
{
    extern __shared__ __half sm[];
    __half* As = sm;
    __half* Bs = sm + 4 * KA_STAGE;
    const __half* A = g_vh    + (size_t)blockIdx.z * (NSEQ * 16 * LDIM);
    const __half* B = g_attnh + (size_t)blockIdx.z * (LDIM * LDIM);
    int bm = blockIdx.y * 128, bn = blockIdx.x * 128;
    int tid = threadIdx.x, lane = tid & 31, wid = tid >> 5;
    int wm = wid >> 2, wn = wid & 3, grp = lane >> 2, tig = lane & 3;
    uint32_t sA = s2u(As), sB = s2u(Bs);

    int crow = tid >> 2, cch = (tid & 3) * 8;
    int crow2 = (tid + 256) >> 2, cch2 = ((tid + 256) & 3) * 8;

    int aRow = wm * 64 + (lane & 15);
    int aCol = (lane >> 4) * 8;
    int bRow = wn * 32 + ((lane >> 3) & 2) * 4 + (lane & 7);
    int bCol = ((lane >> 3) & 1) * 8;

    float c[4][4][4] = {};

#pragma unroll
    for (int p = 0; p < 3; p++) {
        int k0 = p * 32;
        cp16(sA + (p * KA_STAGE + crow  * KA_ST + cch ) * 2, A + (size_t)(bm + crow ) * LDIM + k0 + cch );
        cp16(sA + (p * KA_STAGE + crow2 * KA_ST + cch2) * 2, A + (size_t)(bm + crow2) * LDIM + k0 + cch2);
        cp16(sB + (p * KA_STAGE + crow  * KA_ST + cch ) * 2, B + (size_t)(bn + crow ) * LDIM + k0 + cch );
        cp16(sB + (p * KA_STAGE + crow2 * KA_ST + cch2) * 2, B + (size_t)(bn + crow2) * LDIM + k0 + cch2);
        asm volatile("cp.async.commit_group;");
    }

    for (int s = 0; s < 12; s++) {
        asm volatile("cp.async.wait_group 2;");
        __syncthreads();
        if (s + 3 < 12) {
            int buf = (s + 3) & 3, k0 = (s + 3) * 32;
            cp16(sA + (buf * KA_STAGE + crow  * KA_ST + cch ) * 2, A + (size_t)(bm + crow ) * LDIM + k0 + cch );
            cp16(sA + (buf * KA_STAGE + crow2 * KA_ST + cch2) * 2, A + (size_t)(bm + crow2) * LDIM + k0 + cch2);
            cp16(sB + (buf * KA_STAGE + crow  * KA_ST + cch ) * 2, B + (size_t)(bn + crow ) * LDIM + k0 + cch );
            cp16(sB + (buf * KA_STAGE + crow2 * KA_ST + cch2) * 2, B + (size_t)(bn + crow2) * LDIM + k0 + cch2);
        }
        asm volatile("cp.async.commit_group;");

        uint32_t sAb = sA + ((s & 3) * KA_STAGE) * 2;
        uint32_t sBb = sB + ((s & 3) * KA_STAGE) * 2;
#pragma unroll
        for (int ks = 0; ks < 2; ks++) {
            uint32_t a[4][4], bq[2][4];
#pragma unroll
            for (int mt = 0; mt < 4; mt++)
                ldmx4(a[mt], sAb + (((aRow + mt * 16) * KA_ST) + ks * 16 + aCol) * 2);
#pragma unroll
            for (int ng = 0; ng < 2; ng++)
                ldmx4(bq[ng], sBb + (((bRow + ng * 16) * KA_ST) + ks * 16 + bCol) * 2);
#pragma unroll
            for (int mt = 0; mt < 4; mt++)
#pragma unroll
                for (int nt = 0; nt < 4; nt++)
                    mma_f16(c[mt][nt], a[mt], &bq[nt >> 1][(nt & 1) * 2]);
        }
    }

    __syncthreads();
    __half* out_sm = sm;
#pragma unroll
    for (int mt = 0; mt < 4; mt++)
#pragma unroll
        for (int nt = 0; nt < 4; nt++)
#pragma unroll
            for (int q = 0; q < 4; q++) {
                int ml = wm * 64 + mt * 16 + grp + ((q >= 2) ? 8 : 0);
                int cl = wn * 32 + nt * 8 + 2 * tig + (q & 1);
                out_sm[cl * 136 + ml] = __float2half_rn(c[mt][nt][q]);
            }
    __syncthreads();
    {
        __half* plane = g_oh + (size_t)blockIdx.z * TOK * 16;
        int nb16 = bm >> 4;
#pragma unroll
        for (int i = 0; i < 4; i++) {
            int idx = tid + i * 256;
            int n_loc = idx >> 7, l = idx & 127;
            uint4 lo = *(uint4*)&out_sm[l * 136 + n_loc * 16];
            uint4 hi = *(uint4*)&out_sm[l * 136 + n_loc * 16 + 8];
            size_t off = ((size_t)(nb16 + n_loc) * LDIM + bn + l) * 16;
            *(uint4*)(plane + off)     = lo;
            *(uint4*)(plane + off + 8) = hi;
        }
    }
}

// ---------------- kernel 5: register-resident tail, ldmx4t feeds ------------
#define T2_A   0
#define T2_WO  18432
#define T2_W1  27648
#define T2_W2  61440
#define SMEM_TAIL2 98304

__global__ __launch_bounds__(256, 2) void k_tail(
    const float* __restrict__ tgt,
    const float* __restrict__ bo, const float* __restrict__ b1,
    const float* __restrict__ b2,
    const float* __restrict__ g2, const float* __restrict__ bt2,
    float* __restrict__ out)
{
    extern __shared__ char smem[];
    uint32_t sA  = s2u(smem + T2_A);
    uint32_t sWo = s2u(smem + T2_WO);
    uint32_t sW1 = s2u(smem + T2_W1);
    uint32_t sW2 = s2u(smem + T2_W2);

    int r0 = blockIdx.x * 128;
    int tid = threadIdx.x, lane = tid & 31, wid = tid >> 5;
    int grp = lane >> 2, tig = lane & 3, lk = lane & 15;
    int l8 = lane & 7, kq = ((lane >> 3) & 1) * 8, ch8 = (lane >> 4) * 8;
    int m0 = wid * 16;

#pragma unroll
    for (int i = 0; i < 4; i++) {
        int idx = tid + i * 256;
        int row = idx >> 3, piece = idx & 7;
        int h = piece >> 1, half8 = (piece & 1) * 8;
        cp16(sA + (row * 72 + h * 16 + half8) * 2,
             g_oh + ((size_t)h * TOK + r0 + row) * 16 + half8);
    }
#pragma unroll
    for (int i = 0; i < 2; i++) {
        int idx = tid + i * 256;
        int row = idx >> 3, ch = (idx & 7) * 8;
        cp16(sWo + (row * 72 + ch) * 2, g_Woh + row * 64 + ch);
    }
    asm volatile("cp.async.commit_group;");
#pragma unroll
    for (int i = 0; i < 8; i++) {
        int idx = tid + i * 256;
        int row = idx >> 5, ch = (idx & 31) * 8;
        cp16(sW1 + (row * 264 + ch) * 2, g_W1h + row * DFF + ch);
    }
#pragma unroll
    for (int i = 0; i < 8; i++) {
        int idx = tid + i * 256;
        int row = idx >> 3, ch = (idx & 7) * 8;
        cp16(sW2 + (row * 72 + ch) * 2, g_W2h + row * 64 + ch);
    }
    asm volatile("cp.async.commit_group;");

    float2 tA[8], tB[8];
    {
        const float* ta = tgt + (size_t)(r0 + m0 + grp) * 64 + 2 * tig;
        const float* tb = tgt + (size_t)(r0 + m0 + grp + 8) * 64 + 2 * tig;
#pragma unroll
        for (int nt = 0; nt < 8; nt++) {
            tA[nt] = __ldg((const float2*)(ta + nt * 8));
            tB[nt] = __ldg((const float2*)(tb + nt * 8));
        }
    }

    asm volatile("cp.async.wait_group 1;");
    __syncthreads();

    // GEMM0: raw = A @ Wo + bo + tgt (ldmx4t Wo feeds)
    float raw[8][4];
#pragma unroll
    for (int nt = 0; nt < 8; nt++)
#pragma unroll
        for (int q = 0; q < 4; q++) raw[nt][q] = 0.f;
    {
        int aRow = m0 + lk;
        int aCol = (lane >> 4) * 8;
#pragma unroll
        for (int kw = 0; kw < 4; kw++) {
            uint32_t a[4];
            ldmx4(a, sA + (aRow * 72 + kw * 16 + aCol) * 2);
#pragma unroll
            for (int j = 0; j < 4; j++) {
                uint32_t b4[4];
                ldmx4t(b4, sWo + ((kw * 16 + l8 + kq) * 72 + j * 16 + ch8) * 2);
                mma_f16(raw[2 * j    ], a, &b4[0]);
                mma_f16(raw[2 * j + 1], a, &b4[2]);
            }
        }
    }
#pragma unroll
    for (int nt = 0; nt < 8; nt++) {
        float2 bv = __ldg((const float2*)(bo + nt * 8 + 2 * tig));
        raw[nt][0] += bv.x + tA[nt].x;
        raw[nt][1] += bv.y + tA[nt].y;
        raw[nt][2] += bv.x + tB[nt].x;
        raw[nt][3] += bv.y + tB[nt].y;
    }

    // LN via quad shuffles
    float sa = 0.f, sb = 0.f;
#pragma unroll
    for (int nt = 0; nt < 8; nt++) {
        sa += raw[nt][0] + raw[nt][1];
        sb += raw[nt][2] + raw[nt][3];
    }
    sa += __shfl_xor_sync(0xffffffffu, sa, 1);
    sa += __shfl_xor_sync(0xffffffffu, sa, 2);
    sb += __shfl_xor_sync(0xffffffffu, sb, 1);
    sb += __shfl_xor_sync(0xffffffffu, sb, 2);
    float mA = sa * (1.f / 64.f), mB = sb * (1.f / 64.f);
    float qa = 0.f, qb = 0.f;
#pragma unroll
    for (int nt = 0; nt < 8; nt++) {
        float d0 = raw[nt][0] - mA, d1 = raw[nt][1] - mA;
        float d2 = raw[nt][2] - mB, d3 = raw[nt][3] - mB;
        qa += d0 * d0 + d1 * d1;
        qb += d2 * d2 + d3 * d3;
    }
    qa += __shfl_xor_sync(0xffffffffu, qa, 1);
    qa += __shfl_xor_sync(0xffffffffu, qa, 2);
    qb += __shfl_xor_sync(0xffffffffu, qb, 1);
    qb += __shfl_xor_sync(0xffffffffu, qb, 2);
    float rA = rsqrtf(qa * (1.f / 64.f) + 1e-5f);
    float rB = rsqrtf(qb * (1.f / 64.f) + 1e-5f);

    uint32_t aLN[4][4];
#pragma unroll
    for (int t = 0; t < 4; t++) {
        int n0 = 2 * t, n1 = 2 * t + 1;
        float2 g0 = __ldg((const float2*)(g2  + n0 * 8 + 2 * tig));
        float2 e0 = __ldg((const float2*)(bt2 + n0 * 8 + 2 * tig));
        float2 g1v = __ldg((const float2*)(g2  + n1 * 8 + 2 * tig));
        float2 e1 = __ldg((const float2*)(bt2 + n1 * 8 + 2 * tig));
        aLN[t][0] = packh2(g0.x * (raw[n0][0] - mA) * rA + e0.x,
                           g0.y * (raw[n0][1] - mA) * rA + e0.y);
        aLN[t][1] = packh2(g0.x * (raw[n0][2] - mB) * rB + e0.x,
                           g0.y * (raw[n0][3] - mB) * rB + e0.y);
        aLN[t][2] = packh2(g1v.x * (raw[n1][0] - mA) * rA + e1.x,
                           g1v.y * (raw[n1][1] - mA) * rA + e1.y);
        aLN[t][3] = packh2(g1v.x * (raw[n1][2] - mB) * rB + e1.x,
                           g1v.y * (raw[n1][3] - mB) * rB + e1.y);
    }

    asm volatile("cp.async.wait_group 0;");
    __syncthreads();

    // fused GEMM1 + GEMM2 with ldmx4t feeds
    float acc2[8][4];
#pragma unroll
    for (int nt = 0; nt < 8; nt++)
#pragma unroll
        for (int q = 0; q < 4; q++) acc2[nt][q] = 0.f;

#pragma unroll
    for (int nc = 0; nc < 16; nc++) {
        float a1c[2][4] = {{0.f}};
#pragma unroll
        for (int kw = 0; kw < 4; kw++) {
            uint32_t b4[4];
            ldmx4t(b4, sW1 + ((kw * 16 + l8 + kq) * 264 + nc * 16 + ch8) * 2);
            mma_f16(a1c[0], aLN[kw], &b4[0]);
            mma_f16(a1c[1], aLN[kw], &b4[2]);
        }
        float2 bc0 = __ldg((const float2*)(b1 + nc * 16 + 2 * tig));
        float2 bc1 = __ldg((const float2*)(b1 + nc * 16 + 8 + 2 * tig));
        uint32_t aH[4];
        aH[0] = packh2(fmaxf(a1c[0][0] + bc0.x, 0.f), fmaxf(a1c[0][1] + bc0.y, 0.f));
        aH[1] = packh2(fmaxf(a1c[0][2] + bc0.x, 0.f), fmaxf(a1c[0][3] + bc0.y, 0.f));
        aH[2] = packh2(fmaxf(a1c[1][0] + bc1.x, 0.f), fmaxf(a1c[1][1] + bc1.y, 0.f));
        aH[3] = packh2(fmaxf(a1c[1][2] + bc1.x, 0.f), fmaxf(a1c[1][3] + bc1.y, 0.f));
#pragma unroll
        for (int j = 0; j < 4; j++) {
            uint32_t b4[4];
            ldmx4t(b4, sW2 + ((nc * 16 + l8 + kq) * 72 + j * 16 + ch8) * 2);
            mma_f16(acc2[2 * j    ], aH, &b4[0]);
            mma_f16(acc2[2 * j + 1], aH, &b4[2]);
        }
    }

    float* oA = out + (size_t)(r0 + m0 + grp) * 64 + 2 * tig;
    float* oB = out + (size_t)(r0 + m0 + grp + 8) * 64 + 2 * tig;
#pragma unroll
    for (int nt = 0; nt < 8; nt++) {
        float2 bv = __ldg((const float2*)(b2 + nt * 8 + 2 * tig));
        float2 vA = make_float2(acc2[nt][0] + bv.x + raw[nt][0],
                                acc2[nt][1] + bv.y + raw[nt][1]);
        float2 vB = make_float2(acc2[nt][2] + bv.x + raw[nt][2],
                                acc2[nt][3] + bv.y + raw[nt][3]);
        *(float2*)(oA + nt * 8) = vA;
        *(float2*)(oB + nt * 8) = vB;
    }
}

// ---------------- launch ------------------------------------------------------
extern "C" void kernel_launch(void* const* d_in, const int* in_sizes, int n_in,
                              void* d_out, int out_size)
{
    const float* src = (const float*)d_in[0];
    const float* tgt = (const float*)d_in[1];
    const float* Wp  = (const float*)d_in[2];
    const float* bp  = (const float*)d_in[3];
    const float* Wm  = (const float*)d_in[4];
    const float* bm  = (const float*)d_in[5];
    const float* Wo  = (const float*)d_in[6];
    const float* bo  = (const float*)d_in[7];
    const float* W1  = (const float*)d_in[8];
    const float* b1  = (const float*)d_in[9];
    const float* W2  = (const float*)d_in[10];
    const float* b2  = (const float*)d_in[11];
    const float* gn  = (const float*)d_in[12];
    const float* btn = (const float*)d_in[13];
    const float* g1  = (const float*)d_in[14];
    const float* bt1 = (const float*)d_in[15];
    const float* g2  = (const float*)d_in[16];
    const float* bt2 = (const float*)d_in[17];
    float* out = (float*)d_out;

    const int smem_attn = 4 * KA_STAGE * 2 * 2;   // 81920
    cudaFuncSetAttribute(k_attn, cudaFuncAttributeMaxDynamicSharedMemorySize, smem_attn);
    cudaFuncSetAttribute(k_tail, cudaFuncAttributeMaxDynamicSharedMemorySize, SMEM_TAIL2);

    k_head<<<NB_HEAD, 256>>>(src, Wp, bp, gn, btn, tgt, Wm, bm, g1, bt1, Wo, W1, W2);
    k_softmax<<<HEADS * LDIM / 8, 256>>>();
    k_attn<<<dim3(LDIM / 128, (NSEQ * 16) / 128, HEADS), 256, smem_attn>>>();
    k_tail<<<TOK / 128, 256, SMEM_TAIL2>>>(tgt, bo, b1, b2, g2, bt2, out);
}